// round 3
// baseline (speedup 1.0000x reference)
#include <cuda_runtime.h>
#include <cstdint>

#define B_ROWS 4096
#define D_IN   2048
#define D_K    4096   // 2 * D_IN (concat)
#define D_HID  16384
#define TOPK   64

// ---- scratch (static __device__ arrays: allocation-free contract) ----
__device__ float g_pre[(size_t)B_ROWS * D_HID];   // 256 MB: encoder pre-activations
__device__ float g_Wtm[(size_t)D_HID * D_IN];     // 128 MB: W_dec_m transposed [h, i]
__device__ float g_Wtp[(size_t)D_HID * D_IN];     // 128 MB: W_dec_p transposed [h, i]
__device__ int   g_idx[B_ROWS * TOPK];
__device__ float g_val[B_ROWS * TOPK];

// ============================================================
// Kernel 1: fp32 encode GEMM.  pre[b,j] = sum_k X[b,k]*W[j,k] + be[j]
// X = concat(x_m, x_p) handled at load time. 128x128 tile, 8x8/thread,
// register-prefetch double buffering.
// ============================================================
__global__ __launch_bounds__(256, 2)
void encode_gemm(const float* __restrict__ xm, const float* __restrict__ xp,
                 const float* __restrict__ W, const float* __restrict__ be)
{
    __shared__ float As[8][128];
    __shared__ float Bs[8][128];

    const int tid = threadIdx.x;
    const int tx = tid & 15;         // N micro
    const int ty = tid >> 4;         // M micro
    const int bx = blockIdx.x;       // N tile (16384/128 = 128)
    const int by = blockIdx.y;       // M tile (4096/128 = 32)

    const int a_m = tid >> 1;
    const int a_k = (tid & 1) * 4;
    const int a_row = by * 128 + a_m;
    const int b_n = tid >> 1;
    const int b_k = (tid & 1) * 4;
    const int b_row = bx * 128 + b_n;

    float acc[8][8];
#pragma unroll
    for (int i = 0; i < 8; i++)
#pragma unroll
        for (int j = 0; j < 8; j++) acc[i][j] = 0.f;

    float4 pa, pb;
    {
        const int gc = a_k;
        const float* srcA = (gc < D_IN) ? (xm + (size_t)a_row * D_IN + gc)
                                        : (xp + (size_t)a_row * D_IN + (gc - D_IN));
        pa = *reinterpret_cast<const float4*>(srcA);
        pb = *reinterpret_cast<const float4*>(W + (size_t)b_row * D_K + b_k);
    }
    As[a_k+0][a_m] = pa.x; As[a_k+1][a_m] = pa.y; As[a_k+2][a_m] = pa.z; As[a_k+3][a_m] = pa.w;
    Bs[b_k+0][b_n] = pb.x; Bs[b_k+1][b_n] = pb.y; Bs[b_k+2][b_n] = pb.z; Bs[b_k+3][b_n] = pb.w;
    __syncthreads();

    for (int kt = 8; kt <= D_K; kt += 8) {
        if (kt < D_K) {
            const int gc = kt + a_k;
            const float* srcA = (gc < D_IN) ? (xm + (size_t)a_row * D_IN + gc)
                                            : (xp + (size_t)a_row * D_IN + (gc - D_IN));
            pa = *reinterpret_cast<const float4*>(srcA);
            pb = *reinterpret_cast<const float4*>(W + (size_t)b_row * D_K + kt + b_k);
        }
#pragma unroll
        for (int k = 0; k < 8; k++) {
            float a[8], bb[8];
            *reinterpret_cast<float4*>(a)    = *reinterpret_cast<const float4*>(&As[k][ty*8]);
            *reinterpret_cast<float4*>(a+4)  = *reinterpret_cast<const float4*>(&As[k][ty*8+4]);
            *reinterpret_cast<float4*>(bb)   = *reinterpret_cast<const float4*>(&Bs[k][tx*8]);
            *reinterpret_cast<float4*>(bb+4) = *reinterpret_cast<const float4*>(&Bs[k][tx*8+4]);
#pragma unroll
            for (int i = 0; i < 8; i++)
#pragma unroll
                for (int j = 0; j < 8; j++)
                    acc[i][j] = fmaf(a[i], bb[j], acc[i][j]);
        }
        __syncthreads();
        if (kt < D_K) {
            As[a_k+0][a_m]=pa.x; As[a_k+1][a_m]=pa.y; As[a_k+2][a_m]=pa.z; As[a_k+3][a_m]=pa.w;
            Bs[b_k+0][b_n]=pb.x; Bs[b_k+1][b_n]=pb.y; Bs[b_k+2][b_n]=pb.z; Bs[b_k+3][b_n]=pb.w;
            __syncthreads();
        }
    }

#pragma unroll
    for (int i = 0; i < 8; i++) {
        const int row = by*128 + ty*8 + i;
        float* dst = g_pre + (size_t)row * D_HID + bx*128 + tx*8;
#pragma unroll
        for (int j0 = 0; j0 < 8; j0 += 4) {
            const int col = bx*128 + tx*8 + j0;
            float4 v;
            v.x = acc[i][j0+0] + be[col+0];
            v.y = acc[i][j0+1] + be[col+1];
            v.z = acc[i][j0+2] + be[col+2];
            v.w = acc[i][j0+3] + be[col+3];
            *reinterpret_cast<float4*>(dst + j0) = v;
        }
    }
}

// ============================================================
// Kernel 2: transpose W_dec_{m,p} [2048, 16384] -> Wt [16384, 2048]
// ============================================================
__global__ __launch_bounds__(256)
void transpose_wdec(const float* __restrict__ Wm, const float* __restrict__ Wp)
{
    const float* src = blockIdx.z ? Wp : Wm;
    float* dst = blockIdx.z ? g_Wtp : g_Wtm;

    __shared__ float tile[32][33];
    const int x = blockIdx.x * 32 + threadIdx.x;   // h (0..16383)
    const int y = blockIdx.y * 32 + threadIdx.y;   // i (0..2047), 8 thread-rows
#pragma unroll
    for (int r = 0; r < 32; r += 8)
        tile[threadIdx.y + r][threadIdx.x] = src[(size_t)(y + r) * D_HID + x];
    __syncthreads();
    const int xo = blockIdx.y * 32 + threadIdx.x;  // i
    const int yo = blockIdx.x * 32 + threadIdx.y;  // h
#pragma unroll
    for (int r = 0; r < 32; r += 8)
        dst[(size_t)(yo + r) * D_IN + xo] = tile[threadIdx.x][threadIdx.y + r];
}

// ============================================================
// Kernel 3: per-row exact top-64 via 4-level radix select on
// order-preserving uint keys; jax-compatible lowest-index tie-break.
// Writes dense z into d_out and compact (idx, val) lists for decode.
// ============================================================
__device__ __forceinline__ unsigned f2key(float f) {
    unsigned u = __float_as_uint(f);
    return (u & 0x80000000u) ? ~u : (u | 0x80000000u);
}

__global__ __launch_bounds__(256)
void topk_kernel(float* __restrict__ out)
{
    const int b = blockIdx.x;
    const float* row = g_pre + (size_t)b * D_HID;
    float* zrow = out + (size_t)2 * B_ROWS * D_IN + (size_t)b * D_HID;
    const int t = threadIdx.x;
    const int lane = t & 31;

    __shared__ unsigned hist[256];
    __shared__ unsigned s_prefix;
    __shared__ int s_kk, s_eqc, s_tiecnt, s_outcnt;
    __shared__ int tielist[256];

    if (t == 0) { s_prefix = 0u; s_kk = TOPK; s_tiecnt = 0; s_outcnt = 0; }

    for (int level = 0; level < 4; level++) {
        const int shift = 24 - 8 * level;
        hist[t] = 0;
        __syncthreads();
        const unsigned prefix = s_prefix;
        const unsigned pmask = (level == 0) ? 0u : (0xFFFFFFFFu << (shift + 8));
        for (int i = t; i < D_HID; i += 256) {
            const unsigned key = f2key(row[i]);
            const bool cand = ((key & pmask) == prefix);
            const unsigned act = __ballot_sync(0xFFFFFFFFu, cand);
            if (cand) {
                const unsigned bucket = (key >> shift) & 0xFFu;
                const unsigned m = __match_any_sync(act, bucket);
                if ((int)(__ffs(m) - 1) == lane)
                    atomicAdd(&hist[bucket], (unsigned)__popc(m));
            }
        }
        __syncthreads();
        if (t == 0) {
            const int kk = s_kk;
            unsigned cum = 0;
            int sel = 0;
            for (int bb2 = 255; bb2 >= 0; --bb2) {
                if (cum + hist[bb2] >= (unsigned)kk) { sel = bb2; break; }
                cum += hist[bb2];
            }
            s_kk = kk - (int)cum;
            s_prefix = prefix | ((unsigned)sel << shift);
            s_eqc = (int)hist[sel];
        }
        __syncthreads();
    }

    const unsigned tau = s_prefix;          // key of the 64th-largest value
    const int tneed = s_kk;                 // how many ==tau to include (>=1)
    const bool tiebreak = (s_eqc != tneed); // need lowest-index selection among ties

    if (tiebreak) {
        for (int i = t; i < D_HID; i += 256) {
            if (f2key(row[i]) == tau) {
                const int p = atomicAdd(&s_tiecnt, 1);
                if (p < 256) tielist[p] = i;
            }
        }
        __syncthreads();
        if (t == 0) {  // insertion-sort the (tiny) tie list ascending by index
            int n = s_tiecnt; if (n > 256) n = 256;
            for (int i = 1; i < n; i++) {
                const int v = tielist[i]; int j = i - 1;
                while (j >= 0 && tielist[j] > v) { tielist[j+1] = tielist[j]; j--; }
                tielist[j+1] = v;
            }
        }
        __syncthreads();
    }

    for (int i = t; i < D_HID; i += 256) {
        const float v = row[i];
        const unsigned key = f2key(v);
        bool take = false;
        if (key > tau) take = true;
        else if (key == tau) {
            if (!tiebreak) take = true;
            else {
                for (int r = 0; r < tneed; r++)
                    if (tielist[r] == i) { take = true; break; }
            }
        }
        zrow[i] = take ? fmaxf(v, 0.f) : 0.f;
        if (take) {
            const int p = atomicAdd(&s_outcnt, 1);
            g_idx[b * TOPK + p] = i;
            g_val[b * TOPK + p] = fmaxf(v, 0.f);
        }
    }
}

// ============================================================
// Kernel 4: sparse fp32 decode. rec[b,i] = sum_j val_j * Wt[idx_j, i]
// One CTA per row b; both decoders; coalesced 8KB row reads of Wt.
// ============================================================
__global__ __launch_bounds__(256)
void decode_kernel(float* __restrict__ out)
{
    const int b = blockIdx.x;
    const int t = threadIdx.x;

    __shared__ int   sidx[TOPK];
    __shared__ float sval[TOPK];
    if (t < TOPK) { sidx[t] = g_idx[b * TOPK + t]; sval[t] = g_val[b * TOPK + t]; }
    __syncthreads();

    float am[8], ap[8];
#pragma unroll
    for (int s = 0; s < 8; s++) { am[s] = 0.f; ap[s] = 0.f; }

#pragma unroll 1
    for (int j = 0; j < TOPK; j++) {
        const int h = sidx[j];
        const float v = sval[j];
        const float* wm = g_Wtm + (size_t)h * D_IN;
        const float* wp = g_Wtp + (size_t)h * D_IN;
#pragma unroll
        for (int s = 0; s < 8; s++) {
            const int c = t + s * 256;
            am[s] = fmaf(v, wm[c], am[s]);
            ap[s] = fmaf(v, wp[c], ap[s]);
        }
    }

    float* om = out + (size_t)b * D_IN;
    float* op = out + (size_t)B_ROWS * D_IN + (size_t)b * D_IN;
#pragma unroll
    for (int s = 0; s < 8; s++) {
        om[t + s * 256] = am[s];
        op[t + s * 256] = ap[s];
    }
}

// ============================================================
extern "C" void kernel_launch(void* const* d_in, const int* in_sizes, int n_in,
                              void* d_out, int out_size)
{
    const float* xm = (const float*)d_in[0];
    const float* xp = (const float*)d_in[1];
    const float* W  = (const float*)d_in[2];
    const float* be = (const float*)d_in[3];
    const float* Wm = (const float*)d_in[4];
    const float* Wp = (const float*)d_in[5];
    // d_in[6] = k (always 64 for this problem; shapes are static)
    float* out = (float*)d_out;

    dim3 g1(D_HID / 128, B_ROWS / 128);
    encode_gemm<<<g1, 256>>>(xm, xp, W, be);

    dim3 g2(D_HID / 32, D_IN / 32, 2);
    transpose_wdec<<<g2, dim3(32, 8)>>>(Wm, Wp);

    topk_kernel<<<B_ROWS, 256>>>(out);

    decode_kernel<<<B_ROWS, 256>>>(out);
}

// round 7
// speedup vs baseline: 5.0380x; 5.0380x over previous
#include <cuda_runtime.h>
#include <cuda_fp16.h>
#include <cstdint>

#define B_ROWS 4096
#define D_IN   2048
#define D_K    4096
#define D_HID  16384
#define TOPK   64

__device__ float  g_pre[(size_t)B_ROWS * D_HID];
__device__ __half g_Xh[(size_t)B_ROWS * D_K];
__device__ __half g_Wh[(size_t)D_HID * D_K];
__device__ float  g_Wtm[(size_t)D_HID * D_IN];
__device__ float  g_Wtp[(size_t)D_HID * D_IN];
__device__ int    g_idx[B_ROWS * TOPK];
__device__ float  g_val[B_ROWS * TOPK];

// ---------------- helpers ----------------
__device__ __forceinline__ uint32_t smem_u32(const void* p) {
    uint32_t a;
    asm("{ .reg .u64 t; cvta.to.shared.u64 t, %1; cvt.u32.u64 %0, t; }" : "=r"(a) : "l"(p));
    return a;
}
__device__ __forceinline__ void cp16(uint32_t dst, const void* src) {
    asm volatile("cp.async.cg.shared.global [%0], [%1], 16;" :: "r"(dst), "l"(src) : "memory");
}
__device__ __forceinline__ void ldsm4(uint32_t& d0, uint32_t& d1, uint32_t& d2, uint32_t& d3,
                                      uint32_t addr) {
    asm volatile("ldmatrix.sync.aligned.m8n8.x4.shared.b16 {%0,%1,%2,%3}, [%4];"
        : "=r"(d0), "=r"(d1), "=r"(d2), "=r"(d3) : "r"(addr));
}
__device__ __forceinline__ void mma16816(float* c, const uint32_t* a, uint32_t b0, uint32_t b1) {
    asm volatile("mma.sync.aligned.m16n8k16.row.col.f32.f16.f16.f32 "
        "{%0,%1,%2,%3}, {%4,%5,%6,%7}, {%8,%9}, {%0,%1,%2,%3};"
        : "+f"(c[0]), "+f"(c[1]), "+f"(c[2]), "+f"(c[3])
        : "r"(a[0]), "r"(a[1]), "r"(a[2]), "r"(a[3]), "r"(b0), "r"(b1));
}

// ---------------- fp16 conversions ----------------
__global__ __launch_bounds__(256)
void cvt_x(const float* __restrict__ xm, const float* __restrict__ xp)
{
    const int i4 = (blockIdx.x * 256 + threadIdx.x) * 4;
    const int r = i4 >> 12, c = i4 & 4095;
    const float* s = (c < D_IN) ? xm + (size_t)r * D_IN + c
                                : xp + (size_t)r * D_IN + (c - D_IN);
    float4 v = *reinterpret_cast<const float4*>(s);
    __half2 h0 = __floats2half2_rn(v.x, v.y);
    __half2 h1 = __floats2half2_rn(v.z, v.w);
    *reinterpret_cast<__half2*>(g_Xh + i4)     = h0;
    *reinterpret_cast<__half2*>(g_Xh + i4 + 2) = h1;
}
__global__ __launch_bounds__(256)
void cvt_w(const float* __restrict__ W)
{
    const size_t i4 = ((size_t)blockIdx.x * 256 + threadIdx.x) * 4;
    float4 v = *reinterpret_cast<const float4*>(W + i4);
    __half2 h0 = __floats2half2_rn(v.x, v.y);
    __half2 h1 = __floats2half2_rn(v.z, v.w);
    *reinterpret_cast<__half2*>(g_Wh + i4)     = h0;
    *reinterpret_cast<__half2*>(g_Wh + i4 + 2) = h1;
}

// ---------------- fp16 mma.sync encode GEMM: 128x128 tile ----------------
#define KC 32
#define ROWB 80
#define TILEB (128 * ROWB)
#define STGB (2 * TILEB)
#define STAGES 4
#define SMEM_GEMM (STAGES * STGB)   // 81920
#define NCHUNK (D_K / KC)           // 128

__global__ __launch_bounds__(256, 2)
void encode_mma(const float* __restrict__ be)
{
    extern __shared__ __align__(128) char smem[];
    const uint32_t sb = smem_u32(smem);
    const int tid = threadIdx.x;
    const int wid = tid >> 5, ln = tid & 31;
    const int wm = wid >> 2, wn = wid & 3;
    const int mbase = blockIdx.x * 128;
    const int nbase = blockIdx.y * 128;

    float acc[4][4][4];
#pragma unroll
    for (int i = 0; i < 4; i++)
#pragma unroll
        for (int j = 0; j < 4; j++)
#pragma unroll
            for (int q = 0; q < 4; q++) acc[i][j][q] = 0.f;

    auto load_stage = [&](int st, int kc) {
        const uint32_t dA = sb + st * STGB;
        const uint32_t dB = dA + TILEB;
#pragma unroll
        for (int it = 0; it < 2; it++) {
            const int idx = tid + it * 256;
            const int r = idx >> 2, sg = idx & 3;
            cp16(dA + r * ROWB + sg * 16,
                 g_Xh + ((size_t)(mbase + r) * D_K + kc * KC + sg * 8));
        }
#pragma unroll
        for (int it = 0; it < 2; it++) {
            const int idx = tid + it * 256;
            const int r = idx >> 2, sg = idx & 3;
            cp16(dB + r * ROWB + sg * 16,
                 g_Wh + ((size_t)(nbase + r) * D_K + kc * KC + sg * 8));
        }
        asm volatile("cp.async.commit_group;" ::: "memory");
    };

    load_stage(0, 0); load_stage(1, 1); load_stage(2, 2);

    const int a_row = (ln & 15);
    const int a_kb  = ((ln >> 4) & 1) * 16;
    const int b_row = (ln & 7) + ((ln >> 4) & 1) * 8;
    const int b_kb  = ((ln >> 3) & 1) * 16;

    for (int kc = 0; kc < NCHUNK; kc++) {
        // FIX: tail iterations must fully drain — with no new commits, wait_group 2
        // no longer guarantees this iteration's chunk has landed.
        if (kc < NCHUNK - 2)
            asm volatile("cp.async.wait_group 2;" ::: "memory");
        else
            asm volatile("cp.async.wait_group 0;" ::: "memory");
        __syncthreads();
        const int st = kc & 3;
        const uint32_t aB = sb + st * STGB;
        const uint32_t bB = aB + TILEB;
#pragma unroll
        for (int ks = 0; ks < 2; ks++) {
            uint32_t a[4][4], b[2][4];
#pragma unroll
            for (int mf = 0; mf < 4; mf++)
                ldsm4(a[mf][0], a[mf][1], a[mf][2], a[mf][3],
                      aB + (wm * 64 + mf * 16 + a_row) * ROWB + ks * 32 + a_kb);
#pragma unroll
            for (int p = 0; p < 2; p++)
                ldsm4(b[p][0], b[p][1], b[p][2], b[p][3],
                      bB + (wn * 32 + p * 16 + b_row) * ROWB + ks * 32 + b_kb);
#pragma unroll
            for (int mf = 0; mf < 4; mf++)
#pragma unroll
                for (int nf = 0; nf < 4; nf++)
                    mma16816(acc[mf][nf], a[mf],
                             b[nf >> 1][(nf & 1) * 2], b[nf >> 1][(nf & 1) * 2 + 1]);
        }
        if (kc + 3 < NCHUNK) load_stage((kc + 3) & 3, kc + 3);
    }

    const int g = ln >> 2, tq = ln & 3;
#pragma unroll
    for (int mf = 0; mf < 4; mf++) {
        const int row0 = mbase + wm * 64 + mf * 16 + g;
#pragma unroll
        for (int nf = 0; nf < 4; nf++) {
            const int col = nbase + wn * 32 + nf * 8 + 2 * tq;
            const float b0 = __ldg(be + col), b1 = __ldg(be + col + 1);
            float2 v0 = { acc[mf][nf][0] + b0, acc[mf][nf][1] + b1 };
            float2 v1 = { acc[mf][nf][2] + b0, acc[mf][nf][3] + b1 };
            *reinterpret_cast<float2*>(g_pre + (size_t)row0 * D_HID + col) = v0;
            *reinterpret_cast<float2*>(g_pre + (size_t)(row0 + 8) * D_HID + col) = v1;
        }
    }
}

// ---------------- transpose W_dec ----------------
__global__ __launch_bounds__(256)
void transpose_wdec(const float* __restrict__ Wm, const float* __restrict__ Wp)
{
    const float* src = blockIdx.z ? Wp : Wm;
    float* dst = blockIdx.z ? g_Wtp : g_Wtm;
    __shared__ float tile[32][33];
    const int x = blockIdx.x * 32 + threadIdx.x;
    const int y = blockIdx.y * 32 + threadIdx.y;
#pragma unroll
    for (int r = 0; r < 32; r += 8)
        tile[threadIdx.y + r][threadIdx.x] = src[(size_t)(y + r) * D_HID + x];
    __syncthreads();
    const int xo = blockIdx.y * 32 + threadIdx.x;
    const int yo = blockIdx.x * 32 + threadIdx.y;
#pragma unroll
    for (int r = 0; r < 32; r += 8)
        dst[(size_t)(yo + r) * D_IN + xo] = tile[threadIdx.x][threadIdx.y + r];
}

// ---------------- top-64 with exact fp32 boundary resolve ----------------
__device__ __forceinline__ unsigned f2key(float f) {
    unsigned u = __float_as_uint(f);
    return (u & 0x80000000u) ? ~u : (u | 0x80000000u);
}
__device__ __forceinline__ float key2f(unsigned k) {
    return __uint_as_float((k & 0x80000000u) ? (k & 0x7FFFFFFFu) : ~k);
}
#define MARGIN 0.01f
#define WCAP 256

__global__ __launch_bounds__(256)
void topk_kernel(float* __restrict__ out,
                 const float* __restrict__ xm, const float* __restrict__ xp,
                 const float* __restrict__ W, const float* __restrict__ be)
{
    const int b = blockIdx.x;
    const float* row = g_pre + (size_t)b * D_HID;
    float* zrow = out + (size_t)2 * B_ROWS * D_IN + (size_t)b * D_HID;
    const int t = threadIdx.x, lane = t & 31, wrp = t >> 5;

    __shared__ unsigned hist[256];
    __shared__ unsigned s_prefix;
    __shared__ int s_kk;
    __shared__ float s_x[D_K];
    __shared__ int   win_idx[WCAP];
    __shared__ float win_val[WCAP];
    __shared__ unsigned char win_sel[WCAP];
    __shared__ int s_nwin, s_nhi, s_out;

    if (t == 0) { s_prefix = 0u; s_kk = TOPK; s_nwin = 0; s_nhi = 0; s_out = 0; }

    for (int level = 0; level < 4; level++) {
        const int shift = 24 - 8 * level;
        hist[t] = 0;
        __syncthreads();
        const unsigned prefix = s_prefix;
        const unsigned pmask = level ? (0xFFFFFFFFu << (shift + 8)) : 0u;
        for (int i = t; i < D_HID; i += 256) {
            const unsigned key = f2key(row[i]);
            const bool cand = ((key & pmask) == prefix);
            const unsigned act = __ballot_sync(0xFFFFFFFFu, cand);
            if (cand) {
                const unsigned bkt = (key >> shift) & 0xFFu;
                const unsigned m = __match_any_sync(act, bkt);
                if ((int)(__ffs(m) - 1) == lane)
                    atomicAdd(&hist[bkt], (unsigned)__popc(m));
            }
        }
        __syncthreads();
        if (t == 0) {
            const int kk = s_kk;
            unsigned cum = 0; int sel = 0;
            for (int q = 255; q >= 0; --q) {
                if (cum + hist[q] >= (unsigned)kk) { sel = q; break; }
                cum += hist[q];
            }
            s_kk = kk - (int)cum;
            s_prefix = prefix | ((unsigned)sel << shift);
        }
        __syncthreads();
    }

    const float tau = key2f(s_prefix);
    const float hi = tau + MARGIN, lo = tau - MARGIN;

    for (int j = t; j < D_K; j += 256)
        s_x[j] = (j < D_IN) ? xm[(size_t)b * D_IN + j] : xp[(size_t)b * D_IN + (j - D_IN)];
    for (int i = t; i < D_HID; i += 256) {
        const float v = row[i];
        if (v > hi) atomicAdd(&s_nhi, 1);
        else if (v >= lo) {
            const int p = atomicAdd(&s_nwin, 1);
            if (p < WCAP) win_idx[p] = i;
        }
    }
    __syncthreads();
    const int nwin = min(s_nwin, WCAP);

    for (int wI = wrp; wI < nwin; wI += 8) {
        const float* wr = W + (size_t)win_idx[wI] * D_K;
        float p = 0.f;
        for (int j = lane; j < D_K; j += 32) p = fmaf(s_x[j], __ldg(wr + j), p);
#pragma unroll
        for (int o = 16; o; o >>= 1) p += __shfl_xor_sync(0xFFFFFFFFu, p, o);
        if (lane == 0) win_val[wI] = p + __ldg(be + win_idx[wI]);
    }
    __syncthreads();

    if (t == 0) {
        for (int i = 1; i < nwin; i++) {
            const int id = win_idx[i]; const float v = win_val[i];
            int j = i - 1;
            while (j >= 0 && (win_val[j] < v || (win_val[j] == v && win_idx[j] > id))) {
                win_val[j+1] = win_val[j]; win_idx[j+1] = win_idx[j]; j--;
            }
            win_val[j+1] = v; win_idx[j+1] = id;
        }
        int need = TOPK - s_nhi;
        if (need < 0) need = 0;
        if (need > nwin) need = nwin;
        for (int i = 0; i < nwin; i++) win_sel[i] = (i < need) ? 1 : 0;
    }
    __syncthreads();

    for (int i = t; i < D_HID; i += 256) {
        const float v = row[i];
        bool take = false; float val = 0.f;
        if (v > hi) { take = true; val = v; }
        else if (v >= lo) {
            for (int q = 0; q < nwin; q++)
                if (win_idx[q] == i) { take = (win_sel[q] != 0); val = win_val[q]; break; }
        }
        const float zr = take ? fmaxf(val, 0.f) : 0.f;
        zrow[i] = zr;
        if (take) {
            const int p = atomicAdd(&s_out, 1);
            g_idx[b * TOPK + p] = i;
            g_val[b * TOPK + p] = zr;
        }
    }
}

// ---------------- sparse decode ----------------
__global__ __launch_bounds__(256)
void decode_kernel(float* __restrict__ out)
{
    const int b = blockIdx.x, t = threadIdx.x;
    __shared__ int   sidx[TOPK];
    __shared__ float sval[TOPK];
    if (t < TOPK) { sidx[t] = g_idx[b * TOPK + t]; sval[t] = g_val[b * TOPK + t]; }
    __syncthreads();

    float am[8], ap[8];
#pragma unroll
    for (int s = 0; s < 8; s++) { am[s] = 0.f; ap[s] = 0.f; }
#pragma unroll 1
    for (int j = 0; j < TOPK; j++) {
        const int h = sidx[j];
        const float v = sval[j];
        const float* wm = g_Wtm + (size_t)h * D_IN;
        const float* wp = g_Wtp + (size_t)h * D_IN;
#pragma unroll
        for (int s = 0; s < 8; s++) {
            const int c = t + s * 256;
            am[s] = fmaf(v, wm[c], am[s]);
            ap[s] = fmaf(v, wp[c], ap[s]);
        }
    }
    float* om = out + (size_t)b * D_IN;
    float* op = out + (size_t)B_ROWS * D_IN + (size_t)b * D_IN;
#pragma unroll
    for (int s = 0; s < 8; s++) { om[t + s*256] = am[s]; op[t + s*256] = ap[s]; }
}

// ---------------- host ----------------
extern "C" void kernel_launch(void* const* d_in, const int* in_sizes, int n_in,
                              void* d_out, int out_size)
{
    const float* xm = (const float*)d_in[0];
    const float* xp = (const float*)d_in[1];
    const float* W  = (const float*)d_in[2];
    const float* be = (const float*)d_in[3];
    const float* Wm = (const float*)d_in[4];
    const float* Wp = (const float*)d_in[5];
    float* out = (float*)d_out;

    cvt_x<<<(B_ROWS * D_K / 4) / 256, 256>>>(xm, xp);
    cvt_w<<<((size_t)D_HID * D_K / 4) / 256, 256>>>(W);

    cudaFuncSetAttribute(encode_mma, cudaFuncAttributeMaxDynamicSharedMemorySize, SMEM_GEMM);
    dim3 g1(B_ROWS / 128, D_HID / 128);
    encode_mma<<<g1, 256, SMEM_GEMM>>>(be);

    dim3 g2(D_HID / 32, D_IN / 32, 2);
    transpose_wdec<<<g2, dim3(32, 8)>>>(Wm, Wp);

    topk_kernel<<<B_ROWS, 256>>>(out, xm, xp, W, be);

    decode_kernel<<<B_ROWS, 256>>>(out);
}

// round 8
// speedup vs baseline: 5.0536x; 1.0031x over previous
#include <cuda_runtime.h>
#include <cuda_fp16.h>
#include <cstdint>

#define B_ROWS 4096
#define D_IN   2048
#define D_K    4096
#define D_HID  16384
#define TOPK   64

__device__ float  g_pre[(size_t)B_ROWS * D_HID];
__device__ __half g_Xh[(size_t)B_ROWS * D_K];
__device__ __half g_Wh[(size_t)D_HID * D_K];
__device__ float  g_Wtm[(size_t)D_HID * D_IN];
__device__ float  g_Wtp[(size_t)D_HID * D_IN];
__device__ int    g_idx[B_ROWS * TOPK];
__device__ float  g_val[B_ROWS * TOPK];

// ---------------- helpers ----------------
__device__ __forceinline__ uint32_t smem_u32(const void* p) {
    uint32_t a;
    asm("{ .reg .u64 t; cvta.to.shared.u64 t, %1; cvt.u32.u64 %0, t; }" : "=r"(a) : "l"(p));
    return a;
}
__device__ __forceinline__ void cp16(uint32_t dst, const void* src) {
    asm volatile("cp.async.cg.shared.global [%0], [%1], 16;" :: "r"(dst), "l"(src) : "memory");
}
__device__ __forceinline__ void ldsm4(uint32_t& d0, uint32_t& d1, uint32_t& d2, uint32_t& d3,
                                      uint32_t addr) {
    asm volatile("ldmatrix.sync.aligned.m8n8.x4.shared.b16 {%0,%1,%2,%3}, [%4];"
        : "=r"(d0), "=r"(d1), "=r"(d2), "=r"(d3) : "r"(addr));
}
__device__ __forceinline__ void mma16816(float* c, const uint32_t* a, uint32_t b0, uint32_t b1) {
    asm volatile("mma.sync.aligned.m16n8k16.row.col.f32.f16.f16.f32 "
        "{%0,%1,%2,%3}, {%4,%5,%6,%7}, {%8,%9}, {%0,%1,%2,%3};"
        : "+f"(c[0]), "+f"(c[1]), "+f"(c[2]), "+f"(c[3])
        : "r"(a[0]), "r"(a[1]), "r"(a[2]), "r"(a[3]), "r"(b0), "r"(b1));
}

// ---------------- fp16 conversions ----------------
__global__ __launch_bounds__(256)
void cvt_x(const float* __restrict__ xm, const float* __restrict__ xp)
{
    const int i4 = (blockIdx.x * 256 + threadIdx.x) * 4;
    const int r = i4 >> 12, c = i4 & 4095;
    const float* s = (c < D_IN) ? xm + (size_t)r * D_IN + c
                                : xp + (size_t)r * D_IN + (c - D_IN);
    float4 v = *reinterpret_cast<const float4*>(s);
    __half2 h0 = __floats2half2_rn(v.x, v.y);
    __half2 h1 = __floats2half2_rn(v.z, v.w);
    *reinterpret_cast<__half2*>(g_Xh + i4)     = h0;
    *reinterpret_cast<__half2*>(g_Xh + i4 + 2) = h1;
}
__global__ __launch_bounds__(256)
void cvt_w(const float* __restrict__ W)
{
    const size_t i4 = ((size_t)blockIdx.x * 256 + threadIdx.x) * 4;
    float4 v = *reinterpret_cast<const float4*>(W + i4);
    __half2 h0 = __floats2half2_rn(v.x, v.y);
    __half2 h1 = __floats2half2_rn(v.z, v.w);
    *reinterpret_cast<__half2*>(g_Wh + i4)     = h0;
    *reinterpret_cast<__half2*>(g_Wh + i4 + 2) = h1;
}

// ---------------- fp16 mma.sync encode GEMM: 128x256 tile ----------------
#define KC 32
#define ROWB 80
#define A_TILEB (128 * ROWB)          // 10240
#define B_TILEB (256 * ROWB)          // 20480
#define STGB (A_TILEB + B_TILEB)      // 30720
#define STAGES 4
#define SMEM_GEMM (STAGES * STGB)     // 122880
#define NCHUNK (D_K / KC)             // 128

__global__ __launch_bounds__(512, 1)
void encode_mma(const float* __restrict__ be)
{
    extern __shared__ __align__(128) char smem[];
    const uint32_t sb = smem_u32(smem);
    const int tid = threadIdx.x;
    const int wid = tid >> 5, ln = tid & 31;
    const int wm = wid >> 2, wn = wid & 3;          // 4 x 4 warp grid
    const int mbase = blockIdx.x * 128;
    const int nbase = blockIdx.y * 256;

    float acc[2][8][4];
#pragma unroll
    for (int i = 0; i < 2; i++)
#pragma unroll
        for (int j = 0; j < 8; j++)
#pragma unroll
            for (int q = 0; q < 4; q++) acc[i][j][q] = 0.f;

    auto load_stage = [&](int st, int kc) {
        const uint32_t dA = sb + st * STGB;
        const uint32_t dB = dA + A_TILEB;
        {   // A: 512 x 16B, one per thread
            const int r = tid >> 2, sg = tid & 3;
            cp16(dA + r * ROWB + sg * 16,
                 g_Xh + ((size_t)(mbase + r) * D_K + kc * KC + sg * 8));
        }
#pragma unroll
        for (int it = 0; it < 2; it++) {            // B: 1024 x 16B
            const int idx = tid + it * 512;
            const int r = idx >> 2, sg = idx & 3;
            cp16(dB + r * ROWB + sg * 16,
                 g_Wh + ((size_t)(nbase + r) * D_K + kc * KC + sg * 8));
        }
        asm volatile("cp.async.commit_group;" ::: "memory");
    };

    load_stage(0, 0); load_stage(1, 1); load_stage(2, 2);

    const int a_row = (ln & 15);
    const int a_kb  = ((ln >> 4) & 1) * 16;
    const int b_row = (ln & 7) + ((ln >> 4) & 1) * 8;
    const int b_kb  = ((ln >> 3) & 1) * 16;

    for (int kc = 0; kc < NCHUNK; kc++) {
        if (kc < NCHUNK - 2)
            asm volatile("cp.async.wait_group 2;" ::: "memory");
        else
            asm volatile("cp.async.wait_group 0;" ::: "memory");
        __syncthreads();
        const int st = kc & 3;
        const uint32_t aB = sb + st * STGB;
        const uint32_t bB = aB + A_TILEB;
#pragma unroll
        for (int ks = 0; ks < 2; ks++) {
            uint32_t a[2][4], b[4][4];
#pragma unroll
            for (int mf = 0; mf < 2; mf++)
                ldsm4(a[mf][0], a[mf][1], a[mf][2], a[mf][3],
                      aB + (wm * 32 + mf * 16 + a_row) * ROWB + ks * 32 + a_kb);
#pragma unroll
            for (int p = 0; p < 4; p++)
                ldsm4(b[p][0], b[p][1], b[p][2], b[p][3],
                      bB + (wn * 64 + p * 16 + b_row) * ROWB + ks * 32 + b_kb);
#pragma unroll
            for (int mf = 0; mf < 2; mf++)
#pragma unroll
                for (int nf = 0; nf < 8; nf++)
                    mma16816(acc[mf][nf], a[mf],
                             b[nf >> 1][(nf & 1) * 2], b[nf >> 1][(nf & 1) * 2 + 1]);
        }
        if (kc + 3 < NCHUNK) load_stage((kc + 3) & 3, kc + 3);
    }

    const int g = ln >> 2, tq = ln & 3;
#pragma unroll
    for (int mf = 0; mf < 2; mf++) {
        const int row0 = mbase + wm * 32 + mf * 16 + g;
#pragma unroll
        for (int nf = 0; nf < 8; nf++) {
            const int col = nbase + wn * 64 + nf * 8 + 2 * tq;
            const float b0 = __ldg(be + col), b1 = __ldg(be + col + 1);
            float2 v0 = { acc[mf][nf][0] + b0, acc[mf][nf][1] + b1 };
            float2 v1 = { acc[mf][nf][2] + b0, acc[mf][nf][3] + b1 };
            *reinterpret_cast<float2*>(g_pre + (size_t)row0 * D_HID + col) = v0;
            *reinterpret_cast<float2*>(g_pre + (size_t)(row0 + 8) * D_HID + col) = v1;
        }
    }
}

// ---------------- transpose W_dec ----------------
__global__ __launch_bounds__(256)
void transpose_wdec(const float* __restrict__ Wm, const float* __restrict__ Wp)
{
    const float* src = blockIdx.z ? Wp : Wm;
    float* dst = blockIdx.z ? g_Wtp : g_Wtm;
    __shared__ float tile[32][33];
    const int x = blockIdx.x * 32 + threadIdx.x;
    const int y = blockIdx.y * 32 + threadIdx.y;
#pragma unroll
    for (int r = 0; r < 32; r += 8)
        tile[threadIdx.y + r][threadIdx.x] = src[(size_t)(y + r) * D_HID + x];
    __syncthreads();
    const int xo = blockIdx.y * 32 + threadIdx.x;
    const int yo = blockIdx.x * 32 + threadIdx.y;
#pragma unroll
    for (int r = 0; r < 32; r += 8)
        dst[(size_t)(yo + r) * D_IN + xo] = tile[threadIdx.x][threadIdx.y + r];
}

// ---------------- top-64, register-resident row ----------------
__device__ __forceinline__ unsigned f2key(float f) {
    unsigned u = __float_as_uint(f);
    return (u & 0x80000000u) ? ~u : (u | 0x80000000u);
}
__device__ __forceinline__ float key2f(unsigned k) {
    return __uint_as_float((k & 0x80000000u) ? (k & 0x7FFFFFFFu) : ~k);
}
#define MARGIN 0.01f
#define WCAP 256
#define VPT 64   // values per thread (16384 / 256)

__global__ __launch_bounds__(256)
void topk_kernel(float* __restrict__ out,
                 const float* __restrict__ xm, const float* __restrict__ xp,
                 const float* __restrict__ W, const float* __restrict__ be)
{
    const int b = blockIdx.x;
    const float* row = g_pre + (size_t)b * D_HID;
    float* zrow = out + (size_t)2 * B_ROWS * D_IN + (size_t)b * D_HID;
    const int t = threadIdx.x, lane = t & 31, wrp = t >> 5;

    // load entire row into registers (coalesced: i = t + j*256)
    float vreg[VPT];
#pragma unroll
    for (int j = 0; j < VPT; j++) vreg[j] = row[t + j * 256];

    __shared__ unsigned hist[256];
    __shared__ unsigned s_prefix;
    __shared__ int s_kk;
    __shared__ float s_x[D_K];
    __shared__ int   win_idx[WCAP];
    __shared__ float win_val[WCAP];
    __shared__ unsigned char win_sel[WCAP];
    __shared__ int s_nwin, s_nhi, s_out;

    if (t == 0) { s_prefix = 0u; s_kk = TOPK; s_nwin = 0; s_nhi = 0; s_out = 0; }

    for (int level = 0; level < 4; level++) {
        const int shift = 24 - 8 * level;
        hist[t] = 0;
        __syncthreads();
        const unsigned prefix = s_prefix;
        const unsigned pmask = level ? (0xFFFFFFFFu << (shift + 8)) : 0u;
#pragma unroll 4
        for (int j = 0; j < VPT; j++) {
            const unsigned key = f2key(vreg[j]);
            const bool cand = ((key & pmask) == prefix);
            const unsigned act = __ballot_sync(0xFFFFFFFFu, cand);
            if (cand) {
                const unsigned bkt = (key >> shift) & 0xFFu;
                const unsigned m = __match_any_sync(act, bkt);
                if ((int)(__ffs(m) - 1) == lane)
                    atomicAdd(&hist[bkt], (unsigned)__popc(m));
            }
        }
        __syncthreads();
        if (t == 0) {
            const int kk = s_kk;
            unsigned cum = 0; int sel = 0;
            for (int q = 255; q >= 0; --q) {
                if (cum + hist[q] >= (unsigned)kk) { sel = q; break; }
                cum += hist[q];
            }
            s_kk = kk - (int)cum;
            s_prefix = prefix | ((unsigned)sel << shift);
        }
        __syncthreads();
    }

    const float tau = key2f(s_prefix);
    const float hi = tau + MARGIN, lo = tau - MARGIN;

    for (int j = t; j < D_K; j += 256)
        s_x[j] = (j < D_IN) ? xm[(size_t)b * D_IN + j] : xp[(size_t)b * D_IN + (j - D_IN)];
#pragma unroll 4
    for (int j = 0; j < VPT; j++) {
        const float v = vreg[j];
        if (v > hi) atomicAdd(&s_nhi, 1);
        else if (v >= lo) {
            const int p = atomicAdd(&s_nwin, 1);
            if (p < WCAP) win_idx[p] = t + j * 256;
        }
    }
    __syncthreads();
    const int nwin = min(s_nwin, WCAP);

    for (int wI = wrp; wI < nwin; wI += 8) {     // exact fp32 dot per window entry
        const float* wr = W + (size_t)win_idx[wI] * D_K;
        float p = 0.f;
        for (int j = lane; j < D_K; j += 32) p = fmaf(s_x[j], __ldg(wr + j), p);
#pragma unroll
        for (int o = 16; o; o >>= 1) p += __shfl_xor_sync(0xFFFFFFFFu, p, o);
        if (lane == 0) win_val[wI] = p + __ldg(be + win_idx[wI]);
    }
    __syncthreads();

    if (t == 0) {
        for (int i = 1; i < nwin; i++) {         // sort: value desc, index asc
            const int id = win_idx[i]; const float v = win_val[i];
            int j = i - 1;
            while (j >= 0 && (win_val[j] < v || (win_val[j] == v && win_idx[j] > id))) {
                win_val[j+1] = win_val[j]; win_idx[j+1] = win_idx[j]; j--;
            }
            win_val[j+1] = v; win_idx[j+1] = id;
        }
        int need = TOPK - s_nhi;
        if (need < 0) need = 0;
        if (need > nwin) need = nwin;
        for (int i = 0; i < nwin; i++) win_sel[i] = (i < need) ? 1 : 0;
    }
    __syncthreads();

#pragma unroll 4
    for (int j = 0; j < VPT; j++) {
        const int i = t + j * 256;
        const float v = vreg[j];
        bool take = false; float val = 0.f;
        if (v > hi) { take = true; val = v; }
        else if (v >= lo) {
            for (int q = 0; q < nwin; q++)
                if (win_idx[q] == i) { take = (win_sel[q] != 0); val = win_val[q]; break; }
        }
        const float zr = take ? fmaxf(val, 0.f) : 0.f;
        zrow[i] = zr;
        if (take) {
            const int p = atomicAdd(&s_out, 1);
            g_idx[b * TOPK + p] = i;
            g_val[b * TOPK + p] = zr;
        }
    }
}

// ---------------- sparse decode ----------------
__global__ __launch_bounds__(256)
void decode_kernel(float* __restrict__ out)
{
    const int b = blockIdx.x, t = threadIdx.x;
    __shared__ int   sidx[TOPK];
    __shared__ float sval[TOPK];
    if (t < TOPK) { sidx[t] = g_idx[b * TOPK + t]; sval[t] = g_val[b * TOPK + t]; }
    __syncthreads();

    float am[8], ap[8];
#pragma unroll
    for (int s = 0; s < 8; s++) { am[s] = 0.f; ap[s] = 0.f; }
#pragma unroll 1
    for (int j = 0; j < TOPK; j++) {
        const int h = sidx[j];
        const float v = sval[j];
        const float* wm = g_Wtm + (size_t)h * D_IN;
        const float* wp = g_Wtp + (size_t)h * D_IN;
#pragma unroll
        for (int s = 0; s < 8; s++) {
            const int c = t + s * 256;
            am[s] = fmaf(v, wm[c], am[s]);
            ap[s] = fmaf(v, wp[c], ap[s]);
        }
    }
    float* om = out + (size_t)b * D_IN;
    float* op = out + (size_t)B_ROWS * D_IN + (size_t)b * D_IN;
#pragma unroll
    for (int s = 0; s < 8; s++) { om[t + s*256] = am[s]; op[t + s*256] = ap[s]; }
}

// ---------------- host ----------------
extern "C" void kernel_launch(void* const* d_in, const int* in_sizes, int n_in,
                              void* d_out, int out_size)
{
    const float* xm = (const float*)d_in[0];
    const float* xp = (const float*)d_in[1];
    const float* W  = (const float*)d_in[2];
    const float* be = (const float*)d_in[3];
    const float* Wm = (const float*)d_in[4];
    const float* Wp = (const float*)d_in[5];
    float* out = (float*)d_out;

    cvt_x<<<(B_ROWS * D_K / 4) / 256, 256>>>(xm, xp);
    cvt_w<<<((size_t)D_HID * D_K / 4) / 256, 256>>>(W);

    cudaFuncSetAttribute(encode_mma, cudaFuncAttributeMaxDynamicSharedMemorySize, SMEM_GEMM);
    dim3 g1(B_ROWS / 128, D_HID / 256);   // 32 x 64
    encode_mma<<<g1, 512, SMEM_GEMM>>>(be);

    dim3 g2(D_HID / 32, D_IN / 32, 2);
    transpose_wdec<<<g2, dim3(32, 8)>>>(Wm, Wp);

    topk_kernel<<<B_ROWS, 256>>>(out, xm, xp, W, be);

    decode_kernel<<<B_ROWS, 256>>>(out);
}